// round 11
// baseline (speedup 1.0000x reference)
#include <cuda_runtime.h>

// PrototypeLoss: mean_i || features[i] - prototypes[labels[i]] ||^2
// N=131072, D=512, C=1000. Output f32 [1,1].
//
// R6/R7 evidence: identical 60.1us / DRAM~58% across 8x different block
// geometries => shared cap. Model: LTS cap is path-independent; features
// (256MB, DRAM) + prototype rows (256MB, L2 hits) = 512MB through LTS.
// R10 design: counting-sort sample indices by label (labels = 0.5MB, cheap),
// then stream features in label-grouped order with the proto row cached in
// registers => proto LTS traffic ~0. K0 zero/detect, K1 histogram, K2 scan,
// K3 scatter, K4 main.

#define N_SAMPLES 131072
#define DIM 512
#define NUM_CLASSES 1000
#define WARPS_PER_BLOCK 8
#define SAMPLES_PER_WARP 16
#define MAIN_BLOCKS (N_SAMPLES / (WARPS_PER_BLOCK * SAMPLES_PER_WARP))  // 1024

__device__ double g_acc;
__device__ unsigned int g_done;
__device__ int g_labels_are_i32;
__device__ unsigned int g_hist[NUM_CLASSES];
__device__ unsigned int g_cursor[NUM_CLASSES];
__device__ unsigned int g_sorted[N_SAMPLES];   // packed: (label << 17) | idx

// ---------------- K0: zero state + detect label dtype ----------------
// Odd 32-bit words are int64 hi-words (all 0 since labels<1000) or int32
// labels of odd samples (P(all 1024 zero) ~ 0). Reads words [0,2048) — always
// in-bounds (labels buffer >= N*4 bytes).
__global__ void k0_init(const int* __restrict__ labels_as_i32) {
    int t = threadIdx.x;   // 1024 threads
    if (t < NUM_CLASSES) { g_hist[t] = 0u; g_cursor[t] = 0u; }
    if (t == 0) { g_acc = 0.0; g_done = 0u; }
    int odd_nonzero = __syncthreads_or(labels_as_i32[2 * t + 1] != 0);
    if (t == 0) g_labels_are_i32 = odd_nonzero;
}

__device__ __forceinline__ int load_label(const void* labels, int i) {
    long long v = g_labels_are_i32
        ? (long long)((const int*)labels)[i]
        : ((const long long*)labels)[i];
    if (v < 0) v = 0;
    if (v >= NUM_CLASSES) v = NUM_CLASSES - 1;   // defensive clamp
    return (int)v;
}

// ---------------- K1: histogram ----------------
__global__ __launch_bounds__(256) void k1_hist(const void* __restrict__ labels) {
    int i = blockIdx.x * blockDim.x + threadIdx.x;   // exactly N threads
    int lab = load_label(labels, i);
    atomicAdd(&g_hist[lab], 1u);
}

// ---------------- K2: exclusive prefix scan over 1000 bins ----------------
__global__ void k2_scan() {
    __shared__ unsigned int buf[1024];
    int t = threadIdx.x;   // 1024 threads, 1 block
    unsigned int c = (t < NUM_CLASSES) ? g_hist[t] : 0u;
    buf[t] = c;
    __syncthreads();
    #pragma unroll
    for (int off = 1; off < 1024; off <<= 1) {
        unsigned int v = (t >= off) ? buf[t - off] : 0u;
        __syncthreads();
        buf[t] += v;
        __syncthreads();
    }
    if (t < NUM_CLASSES) g_cursor[t] = buf[t] - c;   // exclusive
}

// ---------------- K3: scatter packed (label,idx) into sorted order ----------
__global__ __launch_bounds__(256) void k3_scatter(const void* __restrict__ labels) {
    int i = blockIdx.x * blockDim.x + threadIdx.x;   // exactly N threads
    int lab = load_label(labels, i);
    unsigned int pos = atomicAdd(&g_cursor[lab], 1u);
    g_sorted[pos] = ((unsigned int)lab << 17) | (unsigned int)i;
}

// ---------------- K4: main streaming kernel ----------------
__global__ __launch_bounds__(256) void k4_main(
    const float* __restrict__ feat,
    const float* __restrict__ protos,
    float* __restrict__ out)
{
    const int lane = threadIdx.x & 31;
    const int wid  = threadIdx.x >> 5;

    const unsigned int warp_global = blockIdx.x * WARPS_PER_BLOCK + wid;
    const unsigned int base = warp_global * SAMPLES_PER_WARP;

    unsigned int mypacked = 0;
    if (lane < SAMPLES_PER_WARP) mypacked = g_sorted[base + lane];

    float s = 0.0f;
    int prev_lab = -1;
    float4 b0, b1, b2, b3;   // register-cached proto row slice for this lane
    b0 = b1 = b2 = b3 = make_float4(0.f, 0.f, 0.f, 0.f);

    #pragma unroll
    for (int it = 0; it < SAMPLES_PER_WARP; it++) {
        unsigned int packed = __shfl_sync(0xffffffffu, mypacked, it);
        int lab = (int)(packed >> 17);
        int idx = (int)(packed & 0x1FFFFu);

        if (lab != prev_lab) {   // warp-uniform; rare after label grouping
            const float4* p = (const float4*)(protos + (size_t)lab * DIM);
            b0 = p[lane +  0];
            b1 = p[lane + 32];
            b2 = p[lane + 64];
            b3 = p[lane + 96];
            prev_lab = lab;
        }

        const float4* f = (const float4*)(feat + (size_t)idx * DIM);
        float4 a0 = __ldcs(f + lane +  0);   // evict-first: features read once
        float4 a1 = __ldcs(f + lane + 32);
        float4 a2 = __ldcs(f + lane + 64);
        float4 a3 = __ldcs(f + lane + 96);

        float d;
        d = a0.x - b0.x; s = fmaf(d, d, s);
        d = a0.y - b0.y; s = fmaf(d, d, s);
        d = a0.z - b0.z; s = fmaf(d, d, s);
        d = a0.w - b0.w; s = fmaf(d, d, s);
        d = a1.x - b1.x; s = fmaf(d, d, s);
        d = a1.y - b1.y; s = fmaf(d, d, s);
        d = a1.z - b1.z; s = fmaf(d, d, s);
        d = a1.w - b1.w; s = fmaf(d, d, s);
        d = a2.x - b2.x; s = fmaf(d, d, s);
        d = a2.y - b2.y; s = fmaf(d, d, s);
        d = a2.z - b2.z; s = fmaf(d, d, s);
        d = a2.w - b2.w; s = fmaf(d, d, s);
        d = a3.x - b3.x; s = fmaf(d, d, s);
        d = a3.y - b3.y; s = fmaf(d, d, s);
        d = a3.z - b3.z; s = fmaf(d, d, s);
        d = a3.w - b3.w; s = fmaf(d, d, s);
    }

    // Warp reduce
    #pragma unroll
    for (int o = 16; o > 0; o >>= 1)
        s += __shfl_xor_sync(0xffffffffu, s, o);

    // Block reduce
    __shared__ float warp_sums[WARPS_PER_BLOCK];
    __shared__ bool is_last;
    if (lane == 0) warp_sums[wid] = s;
    __syncthreads();

    if (threadIdx.x == 0) {
        float t = 0.0f;
        #pragma unroll
        for (int i = 0; i < WARPS_PER_BLOCK; i++) t += warp_sums[i];
        atomicAdd(&g_acc, (double)t);
        __threadfence();
        unsigned int done = atomicAdd(&g_done, 1u);
        is_last = (done == (unsigned int)(gridDim.x - 1));
    }
    __syncthreads();

    if (is_last && threadIdx.x == 0) {
        double total = *((volatile double*)&g_acc);
        out[0] = (float)(total / (double)N_SAMPLES);
        // g_acc/g_done re-zeroed by K0 on the next replay.
    }
}

extern "C" void kernel_launch(void* const* d_in, const int* in_sizes, int n_in,
                              void* d_out, int out_size) {
    const float* feat   = (const float*)d_in[0];
    const void*  labels = d_in[1];
    const float* protos = (const float*)d_in[2];
    float* out = (float*)d_out;

    k0_init<<<1, 1024>>>((const int*)labels);
    k1_hist<<<N_SAMPLES / 256, 256>>>(labels);
    k2_scan<<<1, 1024>>>();
    k3_scatter<<<N_SAMPLES / 256, 256>>>(labels);
    k4_main<<<MAIN_BLOCKS, WARPS_PER_BLOCK * 32>>>(feat, protos, out);
}